// round 9
// baseline (speedup 1.0000x reference)
#include <cuda_runtime.h>
#include <cuda_bf16.h>
#include <math.h>
#include <stdint.h>

#define TT 16
#define NN 20000
#define EE 320000
#define CC 128
#define HH 128
#define PP 100000
#define H3 384

#define ROWPAD 136            // bf16 per smem row (272 B = 17 x 16B: odd -> conflict-free ldmatrix)

// ---------------- scratch (device globals; no allocation allowed) ----------------
__device__ float g_bufA[(size_t)TT * NN * HH];
__device__ float g_bufB[(size_t)TT * NN * HH];
__device__ float g_gi[(size_t)TT * NN * H3];
__device__ float g_gh[(size_t)NN * H3];
__device__ float g_hst[(size_t)NN * HH];
__device__ float g_dinv[TT * NN];
__device__ int   g_cnt[TT * NN];
__device__ int   g_rowptr[TT * (NN + 1)];
__device__ int   g_cursor[TT * NN];
__device__ int   g_csrsrc[TT * EE];
// split weights (bf16 hi/lo): [0,16384) W1^T, [16384,32768) W2^T, [32768,49152) W3^T,
// [49152,98304) w_ih, [98304,147456) w_hh   (all stored [n][k], k contiguous, K=128)
__device__ __nv_bfloat16 g_wh[147456];
__device__ __nv_bfloat16 g_wl[147456];

// ---------------- PTX helpers ----------------
__device__ __forceinline__ uint32_t smem_u32(const void* p) {
    uint32_t a;
    asm("{ .reg .u64 t; cvta.to.shared.u64 t, %1; cvt.u32.u64 %0, t; }" : "=r"(a) : "l"(p));
    return a;
}
__device__ __forceinline__ void ldsm_x4(uint32_t* r, uint32_t addr) {
    asm volatile("ldmatrix.sync.aligned.m8n8.x4.shared.b16 {%0,%1,%2,%3}, [%4];"
                 : "=r"(r[0]), "=r"(r[1]), "=r"(r[2]), "=r"(r[3]) : "r"(addr));
}
__device__ __forceinline__ void mma16816(float* d, const uint32_t* a, const uint32_t* b) {
    asm volatile(
        "mma.sync.aligned.m16n8k16.row.col.f32.bf16.bf16.f32 "
        "{%0,%1,%2,%3}, {%4,%5,%6,%7}, {%8,%9}, {%0,%1,%2,%3};"
        : "+f"(d[0]), "+f"(d[1]), "+f"(d[2]), "+f"(d[3])
        : "r"(a[0]), "r"(a[1]), "r"(a[2]), "r"(a[3]), "r"(b[0]), "r"(b[1]));
}
__device__ __forceinline__ uint32_t pack_bf2(__nv_bfloat16 a, __nv_bfloat16 b) {
    uint32_t r;
    asm("mov.b32 %0, {%1, %2};" : "=r"(r) : "h"(*(uint16_t*)&a), "h"(*(uint16_t*)&b));
    return r;
}

// ---------------- small utility kernels ----------------
__global__ void zero_kernel() {
    int idx = blockIdx.x * blockDim.x + threadIdx.x;
    if (idx < TT * NN) g_cnt[idx] = 0;
    if (idx < NN * HH) g_hst[idx] = 0.f;
}

__global__ void deg_kernel(const int* __restrict__ ei) {
    int idx = blockIdx.x * blockDim.x + threadIdx.x;
    if (idx >= TT * EE) return;
    int t = idx / EE, e = idx - t * EE;
    int dst = ei[(size_t)t * 2 * EE + EE + e];
    atomicAdd(&g_cnt[t * NN + dst], 1);
}

__global__ void dinv_kernel() {
    int idx = blockIdx.x * blockDim.x + threadIdx.x;
    if (idx >= TT * NN) return;
    g_dinv[idx] = rsqrtf((float)g_cnt[idx] + 1.0f);
}

__global__ void scan_kernel() {
    const int CH = 79;
    int t = blockIdx.x;
    int tx = threadIdx.x;
    int base = t * NN;
    int st = tx * CH, en = min(st + CH, NN);
    int s = 0;
    for (int i = st; i < en; i++) s += g_cnt[base + i];
    __shared__ int sh[256];
    sh[tx] = s;
    __syncthreads();
    for (int off = 1; off < 256; off <<= 1) {
        int v = (tx >= off) ? sh[tx - off] : 0;
        __syncthreads();
        sh[tx] += v;
        __syncthreads();
    }
    int run = sh[tx] - s;
    int roff = t * (NN + 1);
    for (int i = st; i < en; i++) {
        int c = g_cnt[base + i];
        g_rowptr[roff + i] = run;
        g_cursor[base + i] = run;
        run += c;
    }
    if (tx == 255) g_rowptr[roff + NN] = sh[255];
}

__global__ void fill_kernel(const int* __restrict__ ei) {
    int idx = blockIdx.x * blockDim.x + threadIdx.x;
    if (idx >= TT * EE) return;
    int t = idx / EE, e = idx - t * EE;
    int src = ei[(size_t)t * 2 * EE + e];
    int dst = ei[(size_t)t * 2 * EE + EE + e];
    int pos = atomicAdd(&g_cursor[t * NN + dst], 1);
    g_csrsrc[(size_t)t * EE + pos] = src;
}

// split weights into bf16 hi/lo pairs, storing [n][k] (k contiguous)
__global__ void split_weights(const float* __restrict__ W1, const float* __restrict__ W2,
                              const float* __restrict__ W3, const float* __restrict__ wih,
                              const float* __restrict__ whh) {
    int idx = blockIdx.x * blockDim.x + threadIdx.x;
    if (idx >= 147456) return;
    float x;
    if (idx < 49152) {
        int w = idx / 16384, r = idx - w * 16384;
        int n = r >> 7, k = r & 127;
        const float* W = (w == 0) ? W1 : ((w == 1) ? W2 : W3);
        x = W[k * 128 + n];              // transpose: W is [K][N]
    } else {
        int j = idx - 49152;
        const float* W = (j < 49152) ? wih : whh;
        int r = (j < 49152) ? j : j - 49152;
        x = W[r];                        // already [n][k]
    }
    __nv_bfloat16 h = __float2bfloat16(x);
    g_wh[idx] = h;
    g_wl[idx] = __float2bfloat16(x - __bfloat162float(h));
}

// ---------------- split-bf16 HMMA GEMM: C[M,Ntot] = A[M,128] @ B^T (+bias, *dscale) ----------------
// grid: (ceil(M/128), Ntot/128), block 256 (8 warps: 4 in M x 2 in N).
// Epilogue stages C through smem (reusing the A region) for coalesced float4 row stores.
#define SMEM_MMA (4 * 128 * ROWPAD * 2)
__global__ void __launch_bounds__(256) mma_gemm(
    const float* __restrict__ A, const __nv_bfloat16* __restrict__ Bh,
    const __nv_bfloat16* __restrict__ Bl, float* __restrict__ C,
    int M, int Ntot, const float* __restrict__ bias, const float* __restrict__ dscale)
{
    extern __shared__ __nv_bfloat16 sm[];
    __nv_bfloat16* Ah = sm;                       // [128][ROWPAD]
    __nv_bfloat16* Al = sm + 128 * ROWPAD;
    __nv_bfloat16* Bsh = sm + 2 * 128 * ROWPAD;   // hi
    __nv_bfloat16* Bsl = sm + 3 * 128 * ROWPAD;   // lo

    const int tid = threadIdx.x;
    const int warp = tid >> 5, lane = tid & 31;
    const int wm = warp >> 1, wn = warp & 1;
    const int row0 = blockIdx.x * 128, col0 = blockIdx.y * 128;

#pragma unroll
    for (int i = 0; i < 16; i++) {
        int fi = tid + i * 256;
        int r = fi >> 5;
        int kc = (fi & 31) * 4;
        float4 v = make_float4(0.f, 0.f, 0.f, 0.f);
        int gr = row0 + r;
        if (gr < M) v = *(const float4*)(A + (size_t)gr * 128 + kc);
        __nv_bfloat16 hx = __float2bfloat16(v.x), hy = __float2bfloat16(v.y);
        __nv_bfloat16 hz = __float2bfloat16(v.z), hw = __float2bfloat16(v.w);
        __nv_bfloat16 lx = __float2bfloat16(v.x - __bfloat162float(hx));
        __nv_bfloat16 ly = __float2bfloat16(v.y - __bfloat162float(hy));
        __nv_bfloat16 lz = __float2bfloat16(v.z - __bfloat162float(hz));
        __nv_bfloat16 lw = __float2bfloat16(v.w - __bfloat162float(hw));
        *(uint2*)(Ah + r * ROWPAD + kc) = make_uint2(pack_bf2(hx, hy), pack_bf2(hz, hw));
        *(uint2*)(Al + r * ROWPAD + kc) = make_uint2(pack_bf2(lx, ly), pack_bf2(lz, lw));
    }
#pragma unroll
    for (int i = 0; i < 16; i++) {
        int fi = tid + i * 256;
        int m = fi >> 11;
        int j = fi & 2047;
        int r = j >> 4;
        int kc = (j & 15) * 8;
        const __nv_bfloat16* src = m ? Bl : Bh;
        uint4 v = *(const uint4*)(src + (size_t)(col0 + r) * 128 + kc);
        __nv_bfloat16* dst = m ? Bsl : Bsh;
        *(uint4*)(dst + r * ROWPAD + kc) = v;
    }
    __syncthreads();

    const uint32_t sbase = smem_u32(sm);
    float acc[2][8][4];
#pragma unroll
    for (int mt = 0; mt < 2; mt++)
#pragma unroll
        for (int nt = 0; nt < 8; nt++)
#pragma unroll
            for (int q = 0; q < 4; q++) acc[mt][nt][q] = 0.f;

    const uint32_t a_lane = (uint32_t)((wm * 32 + (lane & 15)) * ROWPAD + (lane >> 4) * 8) * 2;
    const uint32_t b_lane = (uint32_t)((wn * 64 + (lane & 7) + ((lane >> 4) << 3)) * ROWPAD
                                       + ((lane >> 3) & 1) * 8) * 2;

#pragma unroll
    for (int term = 0; term < 3; term++) {
        const uint32_t abase = sbase + ((term == 1) ? (128 * ROWPAD * 2) : 0) + a_lane;
        const uint32_t bbase = sbase + ((term == 2) ? (3 * 128 * ROWPAD * 2) : (2 * 128 * ROWPAD * 2)) + b_lane;
#pragma unroll
        for (int kc = 0; kc < 8; kc++) {
            uint32_t af[2][4], bf[4][4];
#pragma unroll
            for (int mt = 0; mt < 2; mt++)
                ldsm_x4(af[mt], abase + (uint32_t)(mt * 16 * ROWPAD + kc * 16) * 2);
#pragma unroll
            for (int n2 = 0; n2 < 4; n2++)
                ldsm_x4(bf[n2], bbase + (uint32_t)(n2 * 16 * ROWPAD + kc * 16) * 2);
#pragma unroll
            for (int mt = 0; mt < 2; mt++)
#pragma unroll
                for (int nt = 0; nt < 8; nt++)
                    mma16816(acc[mt][nt], af[mt], &bf[nt >> 1][(nt & 1) * 2]);
        }
    }

    // ---- epilogue: stage C in smem (A region, free after mainloop), coalesced out ----
    __syncthreads();
    float* stage = (float*)sm;   // [128][132] f32 = 67.6 KB <= A region 69.6 KB
#pragma unroll
    for (int mt = 0; mt < 2; mt++) {
        int r_lo = wm * 32 + mt * 16 + (lane >> 2);
#pragma unroll
        for (int nt = 0; nt < 8; nt++) {
            int c = wn * 64 + nt * 8 + (lane & 3) * 2;
            stage[r_lo * 132 + c]           = acc[mt][nt][0];
            stage[r_lo * 132 + c + 1]       = acc[mt][nt][1];
            stage[(r_lo + 8) * 132 + c]     = acc[mt][nt][2];
            stage[(r_lo + 8) * 132 + c + 1] = acc[mt][nt][3];
        }
    }
    __syncthreads();
#pragma unroll
    for (int i = 0; i < 16; i++) {
        int fi = tid + i * 256;       // 0..4095 float4
        int r = fi >> 5;              // 0..127
        int c4 = (fi & 31) * 4;       // 0..124
        int gr = row0 + r;
        if (gr >= M) continue;
        float4 v = *(const float4*)&stage[r * 132 + c4];
        if (dscale) {
            float ds = dscale[gr];
            v.x *= ds; v.y *= ds; v.z *= ds; v.w *= ds;
        }
        if (bias) {
            const float* bp = bias + col0 + c4;
            v.x += bp[0]; v.y += bp[1]; v.z += bp[2]; v.w += bp[3];
        }
        *(float4*)(C + (size_t)gr * Ntot + col0 + c4) = v;
    }
}

// ---------------- GCN aggregation: warp-per-node float4 gather on pre-scaled h' ----------------
// hp holds h' = dinv[row] * (X W). out = dinv[i]*(sum_s h'[s] + h'[i]) + bias  (then relu)
__global__ void __launch_bounds__(256) gather_kernel(
    const float* __restrict__ hp, float* __restrict__ outp,
    const float* __restrict__ bias, int relu)
{
    int t = blockIdx.y;
    int warp = threadIdx.x >> 5, lane = threadIdx.x & 31;
    int i = blockIdx.x * 8 + warp;
    if (i >= NN) return;
    int roff = t * (NN + 1);
    int ks = g_rowptr[roff + i];
    int ke = g_rowptr[roff + i + 1];
    const int* __restrict__ srcs = g_csrsrc + (size_t)t * EE;
    const float* __restrict__ hf = hp + (size_t)t * NN * HH;
    int c = lane * 4;
    float4 acc = make_float4(0.f, 0.f, 0.f, 0.f);
    int k = ks;
    for (; k + 1 < ke; k += 2) {
        int s0 = __ldg(srcs + k);
        int s1 = __ldg(srcs + k + 1);
        float4 v0 = *(const float4*)(hf + (size_t)s0 * HH + c);
        float4 v1 = *(const float4*)(hf + (size_t)s1 * HH + c);
        acc.x += v0.x + v1.x; acc.y += v0.y + v1.y;
        acc.z += v0.z + v1.z; acc.w += v0.w + v1.w;
    }
    if (k < ke) {
        int s = __ldg(srcs + k);
        float4 v = *(const float4*)(hf + (size_t)s * HH + c);
        acc.x += v.x; acc.y += v.y; acc.z += v.z; acc.w += v.w;
    }
    float di = g_dinv[t * NN + i];
    float4 hi = *(const float4*)(hf + (size_t)i * HH + c);
    float4 bv = *(const float4*)(bias + c);
    float4 o;
    o.x = di * (acc.x + hi.x) + bv.x;
    o.y = di * (acc.y + hi.y) + bv.y;
    o.z = di * (acc.z + hi.z) + bv.z;
    o.w = di * (acc.w + hi.w) + bv.w;
    if (relu) {
        o.x = fmaxf(o.x, 0.f); o.y = fmaxf(o.y, 0.f);
        o.z = fmaxf(o.z, 0.f); o.w = fmaxf(o.w, 0.f);
    }
    *(float4*)(outp + (size_t)t * NN * HH + (size_t)i * HH + c) = o;
}

// ---------------- GRU elementwise step ----------------
__global__ void gru_elem(int t) {
    int idx = blockIdx.x * blockDim.x + threadIdx.x;
    if (idx >= NN * HH) return;
    int n = idx >> 7, j = idx & 127;
    const float* gi = g_gi + ((size_t)t * NN + n) * H3;
    const float* gh = g_gh + (size_t)n * H3;
    float ir = gi[j], iz = gi[HH + j], in_ = gi[2 * HH + j];
    float hr = gh[j], hz = gh[HH + j], hn = gh[2 * HH + j];
    float hp = g_hst[idx];
    float r = 1.f / (1.f + expf(-(ir + hr)));
    float z = 1.f / (1.f + expf(-(iz + hz)));
    float nn = tanhf(in_ + r * hn);
    g_hst[idx] = (1.f - z) * nn + z * hp;
}

// ---------------- decoder ----------------
__global__ void decode_kernel(const int* __restrict__ ep, float* __restrict__ out) {
    int gid = blockIdx.x * blockDim.x + threadIdx.x;
    int w = gid >> 5, lane = gid & 31;
    if (w >= PP) return;
    int s = ep[w], d = ep[PP + w];
    float4 a = *(const float4*)&g_hst[(size_t)s * HH + lane * 4];
    float4 b = *(const float4*)&g_hst[(size_t)d * HH + lane * 4];
    float v = a.x * b.x + a.y * b.y + a.z * b.z + a.w * b.w;
#pragma unroll
    for (int off = 16; off; off >>= 1) v += __shfl_down_sync(0xffffffffu, v, off);
    if (lane == 0) out[w] = v;
}

// ---------------- launch ----------------
extern "C" void kernel_launch(void* const* d_in, const int* in_sizes, int n_in,
                              void* d_out, int out_size)
{
    const float* x_seq  = (const float*)d_in[0];
    const int* edge_index = (const int*)d_in[1];
    const int* edge_pairs = (const int*)d_in[2];
    const float* W1 = (const float*)d_in[3];
    const float* b1 = (const float*)d_in[4];
    const float* W2 = (const float*)d_in[5];
    const float* b2 = (const float*)d_in[6];
    const float* W3 = (const float*)d_in[7];
    const float* b3 = (const float*)d_in[8];
    const float* w_ih = (const float*)d_in[9];
    const float* w_hh = (const float*)d_in[10];
    const float* b_ih = (const float*)d_in[11];
    const float* b_hh = (const float*)d_in[12];
    float* out = (float*)d_out;

    float *bufA, *bufB, *gi, *gh, *hst, *dinv;
    __nv_bfloat16 *wh, *wl;
    cudaGetSymbolAddress((void**)&bufA, g_bufA);
    cudaGetSymbolAddress((void**)&bufB, g_bufB);
    cudaGetSymbolAddress((void**)&gi,   g_gi);
    cudaGetSymbolAddress((void**)&gh,   g_gh);
    cudaGetSymbolAddress((void**)&hst,  g_hst);
    cudaGetSymbolAddress((void**)&dinv, g_dinv);
    cudaGetSymbolAddress((void**)&wh,   g_wh);
    cudaGetSymbolAddress((void**)&wl,   g_wl);

    cudaFuncSetAttribute(mma_gemm, cudaFuncAttributeMaxDynamicSharedMemorySize, SMEM_MMA);

    // graph prep
    zero_kernel<<<(NN * HH + 255) / 256, 256>>>();
    deg_kernel<<<(TT * EE + 255) / 256, 256>>>(edge_index);
    dinv_kernel<<<(TT * NN + 255) / 256, 256>>>();
    scan_kernel<<<TT, 256>>>();
    fill_kernel<<<(TT * EE + 255) / 256, 256>>>(edge_index);
    split_weights<<<(147456 + 255) / 256, 256>>>(W1, W2, W3, w_ih, w_hh);

    const int MB = (TT * NN + 127) / 128;   // 2500
    dim3 gGather(NN / 8, TT);               // warp-per-node, 8 nodes/block

    // GCN stack; GEMM epilogue pre-scales by dinv (h' = dinv * XW)
    mma_gemm<<<dim3(MB, 1), 256, SMEM_MMA>>>(x_seq, wh,        wl,        bufA, TT * NN, HH, nullptr, dinv);
    gather_kernel<<<gGather, 256>>>(bufA, bufB, b1, 1);
    mma_gemm<<<dim3(MB, 1), 256, SMEM_MMA>>>(bufB, wh + 16384, wl + 16384, bufA, TT * NN, HH, nullptr, dinv);
    gather_kernel<<<gGather, 256>>>(bufA, bufB, b2, 1);
    mma_gemm<<<dim3(MB, 1), 256, SMEM_MMA>>>(bufB, wh + 32768, wl + 32768, bufA, TT * NN, HH, nullptr, dinv);
    gather_kernel<<<gGather, 256>>>(bufA, bufB, b3, 0);
    // feats in bufB

    // GRU input projections (one big GEMM over all frames)
    mma_gemm<<<dim3(MB, 3), 256, SMEM_MMA>>>(bufB, wh + 49152, wl + 49152, gi, TT * NN, H3, b_ih, nullptr);

    // GRU steps: gh GEMM (B resident in smem) + elementwise
    const int MBH = (NN + 127) / 128;       // 157
    for (int t = 0; t < TT; t++) {
        mma_gemm<<<dim3(MBH, 3), 256, SMEM_MMA>>>(hst, wh + 98304, wl + 98304, gh, NN, H3, b_hh, nullptr);
        gru_elem<<<(NN * HH + 255) / 256, 256>>>(t);
    }

    decode_kernel<<<(PP * 32 + 255) / 256, 256>>>(edge_pairs, out);
}

// round 10
// speedup vs baseline: 1.5018x; 1.5018x over previous
#include <cuda_runtime.h>
#include <cuda_bf16.h>
#include <math.h>
#include <stdint.h>

#define TT 16
#define NN 20000
#define EE 320000
#define CC 128
#define HH 128
#define PP 100000
#define H3 384

#define ROWPAD 136            // bf16 per smem row (272 B = 17 x 16B: odd -> conflict-free ldmatrix)

// ---------------- scratch (device globals; no allocation allowed) ----------------
__device__ float g_bufA[(size_t)TT * NN * HH];
__device__ float g_bufB[(size_t)TT * NN * HH];
__device__ float g_gi[(size_t)TT * NN * H3];
__device__ float g_gh[(size_t)NN * H3];
__device__ float g_hst[(size_t)NN * HH];
__device__ float g_dinv[TT * NN];
__device__ int   g_cnt[TT * NN];
__device__ int   g_rowptr[TT * (NN + 1)];
__device__ int   g_cursor[TT * NN];
__device__ int   g_csrsrc[TT * EE];
// split weights (bf16 hi/lo): [0,16384) W1^T, [16384,32768) W2^T, [32768,49152) W3^T,
// [49152,98304) w_ih, [98304,147456) w_hh   (all stored [n][k], k contiguous, K=128)
__device__ __nv_bfloat16 g_wh[147456];
__device__ __nv_bfloat16 g_wl[147456];

// ---------------- PTX helpers ----------------
__device__ __forceinline__ uint32_t smem_u32(const void* p) {
    uint32_t a;
    asm("{ .reg .u64 t; cvta.to.shared.u64 t, %1; cvt.u32.u64 %0, t; }" : "=r"(a) : "l"(p));
    return a;
}
__device__ __forceinline__ void ldsm_x4(uint32_t* r, uint32_t addr) {
    asm volatile("ldmatrix.sync.aligned.m8n8.x4.shared.b16 {%0,%1,%2,%3}, [%4];"
                 : "=r"(r[0]), "=r"(r[1]), "=r"(r[2]), "=r"(r[3]) : "r"(addr));
}
__device__ __forceinline__ void mma16816(float* d, const uint32_t* a, const uint32_t* b) {
    asm volatile(
        "mma.sync.aligned.m16n8k16.row.col.f32.bf16.bf16.f32 "
        "{%0,%1,%2,%3}, {%4,%5,%6,%7}, {%8,%9}, {%0,%1,%2,%3};"
        : "+f"(d[0]), "+f"(d[1]), "+f"(d[2]), "+f"(d[3])
        : "r"(a[0]), "r"(a[1]), "r"(a[2]), "r"(a[3]), "r"(b[0]), "r"(b[1]));
}
__device__ __forceinline__ uint32_t pack_bf2(__nv_bfloat16 a, __nv_bfloat16 b) {
    uint32_t r;
    asm("mov.b32 %0, {%1, %2};" : "=r"(r) : "h"(*(uint16_t*)&a), "h"(*(uint16_t*)&b));
    return r;
}

// ---------------- small utility kernels ----------------
__global__ void zero_kernel() {
    int idx = blockIdx.x * blockDim.x + threadIdx.x;
    if (idx < TT * NN) g_cnt[idx] = 0;
    if (idx < NN * HH) g_hst[idx] = 0.f;
}

__global__ void deg_kernel(const int* __restrict__ ei) {
    int idx = blockIdx.x * blockDim.x + threadIdx.x;
    if (idx >= TT * EE) return;
    int t = idx / EE, e = idx - t * EE;
    int dst = ei[(size_t)t * 2 * EE + EE + e];
    atomicAdd(&g_cnt[t * NN + dst], 1);
}

__global__ void dinv_kernel() {
    int idx = blockIdx.x * blockDim.x + threadIdx.x;
    if (idx >= TT * NN) return;
    g_dinv[idx] = rsqrtf((float)g_cnt[idx] + 1.0f);
}

__global__ void scan_kernel() {
    const int CH = 79;
    int t = blockIdx.x;
    int tx = threadIdx.x;
    int base = t * NN;
    int st = tx * CH, en = min(st + CH, NN);
    int s = 0;
    for (int i = st; i < en; i++) s += g_cnt[base + i];
    __shared__ int sh[256];
    sh[tx] = s;
    __syncthreads();
    for (int off = 1; off < 256; off <<= 1) {
        int v = (tx >= off) ? sh[tx - off] : 0;
        __syncthreads();
        sh[tx] += v;
        __syncthreads();
    }
    int run = sh[tx] - s;
    int roff = t * (NN + 1);
    for (int i = st; i < en; i++) {
        int c = g_cnt[base + i];
        g_rowptr[roff + i] = run;
        g_cursor[base + i] = run;
        run += c;
    }
    if (tx == 255) g_rowptr[roff + NN] = sh[255];
}

__global__ void fill_kernel(const int* __restrict__ ei) {
    int idx = blockIdx.x * blockDim.x + threadIdx.x;
    if (idx >= TT * EE) return;
    int t = idx / EE, e = idx - t * EE;
    int src = ei[(size_t)t * 2 * EE + e];
    int dst = ei[(size_t)t * 2 * EE + EE + e];
    int pos = atomicAdd(&g_cursor[t * NN + dst], 1);
    g_csrsrc[(size_t)t * EE + pos] = src;
}

// split weights into bf16 hi/lo pairs, storing [n][k] (k contiguous)
__global__ void split_weights(const float* __restrict__ W1, const float* __restrict__ W2,
                              const float* __restrict__ W3, const float* __restrict__ wih,
                              const float* __restrict__ whh) {
    int idx = blockIdx.x * blockDim.x + threadIdx.x;
    if (idx >= 147456) return;
    float x;
    if (idx < 49152) {
        int w = idx / 16384, r = idx - w * 16384;
        int n = r >> 7, k = r & 127;
        const float* W = (w == 0) ? W1 : ((w == 1) ? W2 : W3);
        x = W[k * 128 + n];              // transpose: W is [K][N]
    } else {
        int j = idx - 49152;
        const float* W = (j < 49152) ? wih : whh;
        int r = (j < 49152) ? j : j - 49152;
        x = W[r];                        // already [n][k]
    }
    __nv_bfloat16 h = __float2bfloat16(x);
    g_wh[idx] = h;
    g_wl[idx] = __float2bfloat16(x - __bfloat162float(h));
}

// ---------------- split-bf16 HMMA GEMM: C[M,Ntot] = A[M,128] @ B^T (+bias, *dscale) ----------------
#define SMEM_MMA (4 * 128 * ROWPAD * 2)
__global__ void __launch_bounds__(256) mma_gemm(
    const float* __restrict__ A, const __nv_bfloat16* __restrict__ Bh,
    const __nv_bfloat16* __restrict__ Bl, float* __restrict__ C,
    int M, int Ntot, const float* __restrict__ bias, const float* __restrict__ dscale)
{
    extern __shared__ __nv_bfloat16 sm[];
    __nv_bfloat16* Ah = sm;                       // [128][ROWPAD]
    __nv_bfloat16* Al = sm + 128 * ROWPAD;
    __nv_bfloat16* Bsh = sm + 2 * 128 * ROWPAD;   // hi
    __nv_bfloat16* Bsl = sm + 3 * 128 * ROWPAD;   // lo

    const int tid = threadIdx.x;
    const int warp = tid >> 5, lane = tid & 31;
    const int wm = warp >> 1, wn = warp & 1;
    const int row0 = blockIdx.x * 128, col0 = blockIdx.y * 128;

#pragma unroll
    for (int i = 0; i < 16; i++) {
        int fi = tid + i * 256;
        int r = fi >> 5;
        int kc = (fi & 31) * 4;
        float4 v = make_float4(0.f, 0.f, 0.f, 0.f);
        int gr = row0 + r;
        if (gr < M) v = *(const float4*)(A + (size_t)gr * 128 + kc);
        __nv_bfloat16 hx = __float2bfloat16(v.x), hy = __float2bfloat16(v.y);
        __nv_bfloat16 hz = __float2bfloat16(v.z), hw = __float2bfloat16(v.w);
        __nv_bfloat16 lx = __float2bfloat16(v.x - __bfloat162float(hx));
        __nv_bfloat16 ly = __float2bfloat16(v.y - __bfloat162float(hy));
        __nv_bfloat16 lz = __float2bfloat16(v.z - __bfloat162float(hz));
        __nv_bfloat16 lw = __float2bfloat16(v.w - __bfloat162float(hw));
        *(uint2*)(Ah + r * ROWPAD + kc) = make_uint2(pack_bf2(hx, hy), pack_bf2(hz, hw));
        *(uint2*)(Al + r * ROWPAD + kc) = make_uint2(pack_bf2(lx, ly), pack_bf2(lz, lw));
    }
#pragma unroll
    for (int i = 0; i < 16; i++) {
        int fi = tid + i * 256;
        int m = fi >> 11;
        int j = fi & 2047;
        int r = j >> 4;
        int kc = (j & 15) * 8;
        const __nv_bfloat16* src = m ? Bl : Bh;
        uint4 v = *(const uint4*)(src + (size_t)(col0 + r) * 128 + kc);
        __nv_bfloat16* dst = m ? Bsl : Bsh;
        *(uint4*)(dst + r * ROWPAD + kc) = v;
    }
    __syncthreads();

    const uint32_t sbase = smem_u32(sm);
    float acc[2][8][4];
#pragma unroll
    for (int mt = 0; mt < 2; mt++)
#pragma unroll
        for (int nt = 0; nt < 8; nt++)
#pragma unroll
            for (int q = 0; q < 4; q++) acc[mt][nt][q] = 0.f;

    const uint32_t a_lane = (uint32_t)((wm * 32 + (lane & 15)) * ROWPAD + (lane >> 4) * 8) * 2;
    const uint32_t b_lane = (uint32_t)((wn * 64 + (lane & 7) + ((lane >> 4) << 3)) * ROWPAD
                                       + ((lane >> 3) & 1) * 8) * 2;

#pragma unroll
    for (int term = 0; term < 3; term++) {
        const uint32_t abase = sbase + ((term == 1) ? (128 * ROWPAD * 2) : 0) + a_lane;
        const uint32_t bbase = sbase + ((term == 2) ? (3 * 128 * ROWPAD * 2) : (2 * 128 * ROWPAD * 2)) + b_lane;
#pragma unroll
        for (int kc = 0; kc < 8; kc++) {
            uint32_t af[2][4], bf[4][4];
#pragma unroll
            for (int mt = 0; mt < 2; mt++)
                ldsm_x4(af[mt], abase + (uint32_t)(mt * 16 * ROWPAD + kc * 16) * 2);
#pragma unroll
            for (int n2 = 0; n2 < 4; n2++)
                ldsm_x4(bf[n2], bbase + (uint32_t)(n2 * 16 * ROWPAD + kc * 16) * 2);
#pragma unroll
            for (int mt = 0; mt < 2; mt++)
#pragma unroll
                for (int nt = 0; nt < 8; nt++)
                    mma16816(acc[mt][nt], af[mt], &bf[nt >> 1][(nt & 1) * 2]);
        }
    }

#pragma unroll
    for (int mt = 0; mt < 2; mt++) {
        int r_lo = row0 + wm * 32 + mt * 16 + (lane >> 2);
        int r_hi = r_lo + 8;
        float ds_lo = 1.f, ds_hi = 1.f;
        if (dscale) {
            if (r_lo < M) ds_lo = dscale[r_lo];
            if (r_hi < M) ds_hi = dscale[r_hi];
        }
#pragma unroll
        for (int nt = 0; nt < 8; nt++) {
            int gc = col0 + wn * 64 + nt * 8 + (lane & 3) * 2;
            float bx = 0.f, by = 0.f;
            if (bias) { bx = bias[gc]; by = bias[gc + 1]; }
            if (r_lo < M)
                *(float2*)(C + (size_t)r_lo * Ntot + gc) =
                    make_float2(acc[mt][nt][0] * ds_lo + bx, acc[mt][nt][1] * ds_lo + by);
            if (r_hi < M)
                *(float2*)(C + (size_t)r_hi * Ntot + gc) =
                    make_float2(acc[mt][nt][2] * ds_hi + bx, acc[mt][nt][3] * ds_hi + by);
        }
    }
}

// ---------------- GCN aggregation: warp-per-node float4 gather on pre-scaled h' ----------------
// hp holds h' = dinv[row] * (X W). out = dinv[i]*(sum_s h'[s] + h'[i]) + bias  (then relu)
__global__ void __launch_bounds__(256) gather_kernel(
    const float* __restrict__ hp, float* __restrict__ outp,
    const float* __restrict__ bias, int relu)
{
    int t = blockIdx.y;
    int warp = threadIdx.x >> 5, lane = threadIdx.x & 31;
    int i = blockIdx.x * 8 + warp;
    if (i >= NN) return;
    int roff = t * (NN + 1);
    int ks = g_rowptr[roff + i];
    int ke = g_rowptr[roff + i + 1];
    const int* __restrict__ srcs = g_csrsrc + (size_t)t * EE;
    const float* __restrict__ hf = hp + (size_t)t * NN * HH;
    int c = lane * 4;
    float4 acc = make_float4(0.f, 0.f, 0.f, 0.f);
    int k = ks;
    for (; k + 1 < ke; k += 2) {
        int s0 = __ldg(srcs + k);
        int s1 = __ldg(srcs + k + 1);
        float4 v0 = *(const float4*)(hf + (size_t)s0 * HH + c);
        float4 v1 = *(const float4*)(hf + (size_t)s1 * HH + c);
        acc.x += v0.x + v1.x; acc.y += v0.y + v1.y;
        acc.z += v0.z + v1.z; acc.w += v0.w + v1.w;
    }
    if (k < ke) {
        int s = __ldg(srcs + k);
        float4 v = *(const float4*)(hf + (size_t)s * HH + c);
        acc.x += v.x; acc.y += v.y; acc.z += v.z; acc.w += v.w;
    }
    float di = g_dinv[t * NN + i];
    float4 hi = *(const float4*)(hf + (size_t)i * HH + c);
    float4 bv = *(const float4*)(bias + c);
    float4 o;
    o.x = di * (acc.x + hi.x) + bv.x;
    o.y = di * (acc.y + hi.y) + bv.y;
    o.z = di * (acc.z + hi.z) + bv.z;
    o.w = di * (acc.w + hi.w) + bv.w;
    if (relu) {
        o.x = fmaxf(o.x, 0.f); o.y = fmaxf(o.y, 0.f);
        o.z = fmaxf(o.z, 0.f); o.w = fmaxf(o.w, 0.f);
    }
    *(float4*)(outp + (size_t)t * NN * HH + (size_t)i * HH + c) = o;
}

// ---------------- GRU elementwise step ----------------
__global__ void gru_elem(int t) {
    int idx = blockIdx.x * blockDim.x + threadIdx.x;
    if (idx >= NN * HH) return;
    int n = idx >> 7, j = idx & 127;
    const float* gi = g_gi + ((size_t)t * NN + n) * H3;
    const float* gh = g_gh + (size_t)n * H3;
    float ir = gi[j], iz = gi[HH + j], in_ = gi[2 * HH + j];
    float hr = gh[j], hz = gh[HH + j], hn = gh[2 * HH + j];
    float hp = g_hst[idx];
    float r = 1.f / (1.f + expf(-(ir + hr)));
    float z = 1.f / (1.f + expf(-(iz + hz)));
    float nn = tanhf(in_ + r * hn);
    g_hst[idx] = (1.f - z) * nn + z * hp;
}

// ---------------- decoder ----------------
__global__ void decode_kernel(const int* __restrict__ ep, float* __restrict__ out) {
    int gid = blockIdx.x * blockDim.x + threadIdx.x;
    int w = gid >> 5, lane = gid & 31;
    if (w >= PP) return;
    int s = ep[w], d = ep[PP + w];
    float4 a = *(const float4*)&g_hst[(size_t)s * HH + lane * 4];
    float4 b = *(const float4*)&g_hst[(size_t)d * HH + lane * 4];
    float v = a.x * b.x + a.y * b.y + a.z * b.z + a.w * b.w;
#pragma unroll
    for (int off = 16; off; off >>= 1) v += __shfl_down_sync(0xffffffffu, v, off);
    if (lane == 0) out[w] = v;
}

// ---------------- launch ----------------
extern "C" void kernel_launch(void* const* d_in, const int* in_sizes, int n_in,
                              void* d_out, int out_size)
{
    const float* x_seq  = (const float*)d_in[0];
    const int* edge_index = (const int*)d_in[1];
    const int* edge_pairs = (const int*)d_in[2];
    const float* W1 = (const float*)d_in[3];
    const float* b1 = (const float*)d_in[4];
    const float* W2 = (const float*)d_in[5];
    const float* b2 = (const float*)d_in[6];
    const float* W3 = (const float*)d_in[7];
    const float* b3 = (const float*)d_in[8];
    const float* w_ih = (const float*)d_in[9];
    const float* w_hh = (const float*)d_in[10];
    const float* b_ih = (const float*)d_in[11];
    const float* b_hh = (const float*)d_in[12];
    float* out = (float*)d_out;

    float *bufA, *bufB, *gi, *gh, *hst, *dinv;
    __nv_bfloat16 *wh, *wl;
    cudaGetSymbolAddress((void**)&bufA, g_bufA);
    cudaGetSymbolAddress((void**)&bufB, g_bufB);
    cudaGetSymbolAddress((void**)&gi,   g_gi);
    cudaGetSymbolAddress((void**)&gh,   g_gh);
    cudaGetSymbolAddress((void**)&hst,  g_hst);
    cudaGetSymbolAddress((void**)&dinv, g_dinv);
    cudaGetSymbolAddress((void**)&wh,   g_wh);
    cudaGetSymbolAddress((void**)&wl,   g_wl);

    cudaFuncSetAttribute(mma_gemm, cudaFuncAttributeMaxDynamicSharedMemorySize, SMEM_MMA);

    // graph prep
    zero_kernel<<<(NN * HH + 255) / 256, 256>>>();
    deg_kernel<<<(TT * EE + 255) / 256, 256>>>(edge_index);
    dinv_kernel<<<(TT * NN + 255) / 256, 256>>>();
    scan_kernel<<<TT, 256>>>();
    fill_kernel<<<(TT * EE + 255) / 256, 256>>>(edge_index);
    split_weights<<<(147456 + 255) / 256, 256>>>(W1, W2, W3, w_ih, w_hh);

    const int MB = (TT * NN + 127) / 128;   // 2500
    dim3 gGather(NN / 8, TT);               // warp-per-node, 8 nodes/block

    // GCN stack; GEMM epilogue pre-scales by dinv (h' = dinv * XW)
    mma_gemm<<<dim3(MB, 1), 256, SMEM_MMA>>>(x_seq, wh,        wl,        bufA, TT * NN, HH, nullptr, dinv);
    gather_kernel<<<gGather, 256>>>(bufA, bufB, b1, 1);
    mma_gemm<<<dim3(MB, 1), 256, SMEM_MMA>>>(bufB, wh + 16384, wl + 16384, bufA, TT * NN, HH, nullptr, dinv);
    gather_kernel<<<gGather, 256>>>(bufA, bufB, b2, 1);
    mma_gemm<<<dim3(MB, 1), 256, SMEM_MMA>>>(bufB, wh + 32768, wl + 32768, bufA, TT * NN, HH, nullptr, dinv);
    gather_kernel<<<gGather, 256>>>(bufA, bufB, b3, 0);
    // feats in bufB

    // GRU input projections (one big GEMM over all frames)
    mma_gemm<<<dim3(MB, 3), 256, SMEM_MMA>>>(bufB, wh + 49152, wl + 49152, gi, TT * NN, H3, b_ih, nullptr);

    // GRU steps: gh GEMM (B resident in smem) + elementwise
    const int MBH = (NN + 127) / 128;       // 157
    for (int t = 0; t < TT; t++) {
        mma_gemm<<<dim3(MBH, 3), 256, SMEM_MMA>>>(hst, wh + 98304, wl + 98304, gh, NN, H3, b_hh, nullptr);
        gru_elem<<<(NN * HH + 255) / 256, 256>>>(t);
    }

    decode_kernel<<<(PP * 32 + 255) / 256, 256>>>(edge_pairs, out);
}

// round 11
// speedup vs baseline: 1.6461x; 1.0961x over previous
#include <cuda_runtime.h>
#include <cuda_bf16.h>
#include <cuda_fp16.h>
#include <math.h>
#include <stdint.h>

#define TT 16
#define NN 20000
#define EE 320000
#define CC 128
#define HH 128
#define PP 100000
#define H3 384

#define ROWPAD 136            // bf16 per smem row (272 B = 17 x 16B: odd -> conflict-free ldmatrix)

// ---------------- scratch (device globals; no allocation allowed) ----------------
__device__ __half g_hx[(size_t)TT * NN * HH];    // fp16 h' (GEMM out, gather in)
__device__ float g_bufB[(size_t)TT * NN * HH];
__device__ float g_gi[(size_t)TT * NN * H3];
__device__ float g_gh[(size_t)NN * H3];
__device__ float g_hst[(size_t)NN * HH];
__device__ float g_dinv[TT * NN];
__device__ int   g_cnt[TT * NN];
__device__ int   g_rowptr[TT * (NN + 1)];
__device__ int   g_cursor[TT * NN];
__device__ int   g_csrsrc[TT * EE];
// split weights (bf16 hi/lo): [0,16384) W1^T, [16384,32768) W2^T, [32768,49152) W3^T,
// [49152,98304) w_ih, [98304,147456) w_hh   (all stored [n][k], k contiguous, K=128)
__device__ __nv_bfloat16 g_wh[147456];
__device__ __nv_bfloat16 g_wl[147456];

// ---------------- PTX helpers ----------------
__device__ __forceinline__ uint32_t smem_u32(const void* p) {
    uint32_t a;
    asm("{ .reg .u64 t; cvta.to.shared.u64 t, %1; cvt.u32.u64 %0, t; }" : "=r"(a) : "l"(p));
    return a;
}
__device__ __forceinline__ void ldsm_x4(uint32_t* r, uint32_t addr) {
    asm volatile("ldmatrix.sync.aligned.m8n8.x4.shared.b16 {%0,%1,%2,%3}, [%4];"
                 : "=r"(r[0]), "=r"(r[1]), "=r"(r[2]), "=r"(r[3]) : "r"(addr));
}
__device__ __forceinline__ void mma16816(float* d, const uint32_t* a, const uint32_t* b) {
    asm volatile(
        "mma.sync.aligned.m16n8k16.row.col.f32.bf16.bf16.f32 "
        "{%0,%1,%2,%3}, {%4,%5,%6,%7}, {%8,%9}, {%0,%1,%2,%3};"
        : "+f"(d[0]), "+f"(d[1]), "+f"(d[2]), "+f"(d[3])
        : "r"(a[0]), "r"(a[1]), "r"(a[2]), "r"(a[3]), "r"(b[0]), "r"(b[1]));
}
__device__ __forceinline__ uint32_t pack_bf2(__nv_bfloat16 a, __nv_bfloat16 b) {
    uint32_t r;
    asm("mov.b32 %0, {%1, %2};" : "=r"(r) : "h"(*(uint16_t*)&a), "h"(*(uint16_t*)&b));
    return r;
}

// ---------------- small utility kernels ----------------
__global__ void zero_kernel() {
    int idx = blockIdx.x * blockDim.x + threadIdx.x;
    if (idx < TT * NN) g_cnt[idx] = 0;
    if (idx < NN * HH) g_hst[idx] = 0.f;
}

__global__ void deg_kernel(const int* __restrict__ ei) {
    int idx = blockIdx.x * blockDim.x + threadIdx.x;
    if (idx >= TT * EE) return;
    int t = idx / EE, e = idx - t * EE;
    int dst = ei[(size_t)t * 2 * EE + EE + e];
    atomicAdd(&g_cnt[t * NN + dst], 1);
}

__global__ void dinv_kernel() {
    int idx = blockIdx.x * blockDim.x + threadIdx.x;
    if (idx >= TT * NN) return;
    g_dinv[idx] = rsqrtf((float)g_cnt[idx] + 1.0f);
}

__global__ void scan_kernel() {
    const int CH = 79;
    int t = blockIdx.x;
    int tx = threadIdx.x;
    int base = t * NN;
    int st = tx * CH, en = min(st + CH, NN);
    int s = 0;
    for (int i = st; i < en; i++) s += g_cnt[base + i];
    __shared__ int sh[256];
    sh[tx] = s;
    __syncthreads();
    for (int off = 1; off < 256; off <<= 1) {
        int v = (tx >= off) ? sh[tx - off] : 0;
        __syncthreads();
        sh[tx] += v;
        __syncthreads();
    }
    int run = sh[tx] - s;
    int roff = t * (NN + 1);
    for (int i = st; i < en; i++) {
        int c = g_cnt[base + i];
        g_rowptr[roff + i] = run;
        g_cursor[base + i] = run;
        run += c;
    }
    if (tx == 255) g_rowptr[roff + NN] = sh[255];
}

__global__ void fill_kernel(const int* __restrict__ ei) {
    int idx = blockIdx.x * blockDim.x + threadIdx.x;
    if (idx >= TT * EE) return;
    int t = idx / EE, e = idx - t * EE;
    int src = ei[(size_t)t * 2 * EE + e];
    int dst = ei[(size_t)t * 2 * EE + EE + e];
    int pos = atomicAdd(&g_cursor[t * NN + dst], 1);
    g_csrsrc[(size_t)t * EE + pos] = src;
}

// split weights into bf16 hi/lo pairs, storing [n][k] (k contiguous)
__global__ void split_weights(const float* __restrict__ W1, const float* __restrict__ W2,
                              const float* __restrict__ W3, const float* __restrict__ wih,
                              const float* __restrict__ whh) {
    int idx = blockIdx.x * blockDim.x + threadIdx.x;
    if (idx >= 147456) return;
    float x;
    if (idx < 49152) {
        int w = idx / 16384, r = idx - w * 16384;
        int n = r >> 7, k = r & 127;
        const float* W = (w == 0) ? W1 : ((w == 1) ? W2 : W3);
        x = W[k * 128 + n];              // transpose: W is [K][N]
    } else {
        int j = idx - 49152;
        const float* W = (j < 49152) ? wih : whh;
        int r = (j < 49152) ? j : j - 49152;
        x = W[r];                        // already [n][k]
    }
    __nv_bfloat16 h = __float2bfloat16(x);
    g_wh[idx] = h;
    g_wl[idx] = __float2bfloat16(x - __bfloat162float(h));
}

// ---------------- split-bf16 HMMA GEMM: C = A[M,128] @ B^T (+bias, *dscale) ----------------
// If Ch != nullptr, output is written as fp16 to Ch (Ntot must be 128); else fp32 to C.
#define SMEM_MMA (4 * 128 * ROWPAD * 2)
__global__ void __launch_bounds__(256) mma_gemm(
    const float* __restrict__ A, const __nv_bfloat16* __restrict__ Bh,
    const __nv_bfloat16* __restrict__ Bl, float* __restrict__ C,
    int M, int Ntot, const float* __restrict__ bias, const float* __restrict__ dscale,
    __half* __restrict__ Ch)
{
    extern __shared__ __nv_bfloat16 sm[];
    __nv_bfloat16* Ah = sm;                       // [128][ROWPAD]
    __nv_bfloat16* Al = sm + 128 * ROWPAD;
    __nv_bfloat16* Bsh = sm + 2 * 128 * ROWPAD;   // hi
    __nv_bfloat16* Bsl = sm + 3 * 128 * ROWPAD;   // lo

    const int tid = threadIdx.x;
    const int warp = tid >> 5, lane = tid & 31;
    const int wm = warp >> 1, wn = warp & 1;
    const int row0 = blockIdx.x * 128, col0 = blockIdx.y * 128;

#pragma unroll
    for (int i = 0; i < 16; i++) {
        int fi = tid + i * 256;
        int r = fi >> 5;
        int kc = (fi & 31) * 4;
        float4 v = make_float4(0.f, 0.f, 0.f, 0.f);
        int gr = row0 + r;
        if (gr < M) v = *(const float4*)(A + (size_t)gr * 128 + kc);
        __nv_bfloat16 hx = __float2bfloat16(v.x), hy = __float2bfloat16(v.y);
        __nv_bfloat16 hz = __float2bfloat16(v.z), hw = __float2bfloat16(v.w);
        __nv_bfloat16 lx = __float2bfloat16(v.x - __bfloat162float(hx));
        __nv_bfloat16 ly = __float2bfloat16(v.y - __bfloat162float(hy));
        __nv_bfloat16 lz = __float2bfloat16(v.z - __bfloat162float(hz));
        __nv_bfloat16 lw = __float2bfloat16(v.w - __bfloat162float(hw));
        *(uint2*)(Ah + r * ROWPAD + kc) = make_uint2(pack_bf2(hx, hy), pack_bf2(hz, hw));
        *(uint2*)(Al + r * ROWPAD + kc) = make_uint2(pack_bf2(lx, ly), pack_bf2(lz, lw));
    }
#pragma unroll
    for (int i = 0; i < 16; i++) {
        int fi = tid + i * 256;
        int m = fi >> 11;
        int j = fi & 2047;
        int r = j >> 4;
        int kc = (j & 15) * 8;
        const __nv_bfloat16* src = m ? Bl : Bh;
        uint4 v = *(const uint4*)(src + (size_t)(col0 + r) * 128 + kc);
        __nv_bfloat16* dst = m ? Bsl : Bsh;
        *(uint4*)(dst + r * ROWPAD + kc) = v;
    }
    __syncthreads();

    const uint32_t sbase = smem_u32(sm);
    float acc[2][8][4];
#pragma unroll
    for (int mt = 0; mt < 2; mt++)
#pragma unroll
        for (int nt = 0; nt < 8; nt++)
#pragma unroll
            for (int q = 0; q < 4; q++) acc[mt][nt][q] = 0.f;

    const uint32_t a_lane = (uint32_t)((wm * 32 + (lane & 15)) * ROWPAD + (lane >> 4) * 8) * 2;
    const uint32_t b_lane = (uint32_t)((wn * 64 + (lane & 7) + ((lane >> 4) << 3)) * ROWPAD
                                       + ((lane >> 3) & 1) * 8) * 2;

#pragma unroll
    for (int term = 0; term < 3; term++) {
        const uint32_t abase = sbase + ((term == 1) ? (128 * ROWPAD * 2) : 0) + a_lane;
        const uint32_t bbase = sbase + ((term == 2) ? (3 * 128 * ROWPAD * 2) : (2 * 128 * ROWPAD * 2)) + b_lane;
#pragma unroll
        for (int kc = 0; kc < 8; kc++) {
            uint32_t af[2][4], bf[4][4];
#pragma unroll
            for (int mt = 0; mt < 2; mt++)
                ldsm_x4(af[mt], abase + (uint32_t)(mt * 16 * ROWPAD + kc * 16) * 2);
#pragma unroll
            for (int n2 = 0; n2 < 4; n2++)
                ldsm_x4(bf[n2], bbase + (uint32_t)(n2 * 16 * ROWPAD + kc * 16) * 2);
#pragma unroll
            for (int mt = 0; mt < 2; mt++)
#pragma unroll
                for (int nt = 0; nt < 8; nt++)
                    mma16816(acc[mt][nt], af[mt], &bf[nt >> 1][(nt & 1) * 2]);
        }
    }

#pragma unroll
    for (int mt = 0; mt < 2; mt++) {
        int r_lo = row0 + wm * 32 + mt * 16 + (lane >> 2);
        int r_hi = r_lo + 8;
        float ds_lo = 1.f, ds_hi = 1.f;
        if (dscale) {
            if (r_lo < M) ds_lo = dscale[r_lo];
            if (r_hi < M) ds_hi = dscale[r_hi];
        }
#pragma unroll
        for (int nt = 0; nt < 8; nt++) {
            int gc = col0 + wn * 64 + nt * 8 + (lane & 3) * 2;
            float bx = 0.f, by = 0.f;
            if (bias) { bx = bias[gc]; by = bias[gc + 1]; }
            float v0l = acc[mt][nt][0] * ds_lo + bx, v1l = acc[mt][nt][1] * ds_lo + by;
            float v0h = acc[mt][nt][2] * ds_hi + bx, v1h = acc[mt][nt][3] * ds_hi + by;
            if (Ch) {
                if (r_lo < M)
                    *(__half2*)(Ch + (size_t)r_lo * 128 + gc) = __floats2half2_rn(v0l, v1l);
                if (r_hi < M)
                    *(__half2*)(Ch + (size_t)r_hi * 128 + gc) = __floats2half2_rn(v0h, v1h);
            } else {
                if (r_lo < M)
                    *(float2*)(C + (size_t)r_lo * Ntot + gc) = make_float2(v0l, v1l);
                if (r_hi < M)
                    *(float2*)(C + (size_t)r_hi * Ntot + gc) = make_float2(v0h, v1h);
            }
        }
    }
}

// ---------------- GCN aggregation: warp-per-node gather on fp16 h' ----------------
// hp holds h' = dinv[row] * (X W) in fp16. out = dinv[i]*(sum_s h'[s] + h'[i]) + bias (relu)
__global__ void __launch_bounds__(256) gather_kernel(
    const __half* __restrict__ hp, float* __restrict__ outp,
    const float* __restrict__ bias, int relu)
{
    int t = blockIdx.y;
    int warp = threadIdx.x >> 5, lane = threadIdx.x & 31;
    int i = blockIdx.x * 8 + warp;
    if (i >= NN) return;
    int roff = t * (NN + 1);
    int ks = g_rowptr[roff + i];
    int ke = g_rowptr[roff + i + 1];
    const int* __restrict__ srcs = g_csrsrc + (size_t)t * EE;
    const __half* __restrict__ hf = hp + (size_t)t * NN * HH;
    int c = lane * 4;
    float4 acc = make_float4(0.f, 0.f, 0.f, 0.f);
    int k = ks;
    for (; k + 1 < ke; k += 2) {
        int s0 = __ldg(srcs + k);
        int s1 = __ldg(srcs + k + 1);
        uint2 r0 = *(const uint2*)(hf + (size_t)s0 * HH + c);
        uint2 r1 = *(const uint2*)(hf + (size_t)s1 * HH + c);
        float2 a0 = __half22float2(*(const __half2*)&r0.x);
        float2 a1 = __half22float2(*(const __half2*)&r0.y);
        float2 b0 = __half22float2(*(const __half2*)&r1.x);
        float2 b1 = __half22float2(*(const __half2*)&r1.y);
        acc.x += a0.x + b0.x; acc.y += a0.y + b0.y;
        acc.z += a1.x + b1.x; acc.w += a1.y + b1.y;
    }
    if (k < ke) {
        int s = __ldg(srcs + k);
        uint2 r0 = *(const uint2*)(hf + (size_t)s * HH + c);
        float2 a0 = __half22float2(*(const __half2*)&r0.x);
        float2 a1 = __half22float2(*(const __half2*)&r0.y);
        acc.x += a0.x; acc.y += a0.y; acc.z += a1.x; acc.w += a1.y;
    }
    float di = g_dinv[t * NN + i];
    uint2 rs = *(const uint2*)(hf + (size_t)i * HH + c);
    float2 h0 = __half22float2(*(const __half2*)&rs.x);
    float2 h1 = __half22float2(*(const __half2*)&rs.y);
    float4 bv = *(const float4*)(bias + c);
    float4 o;
    o.x = di * (acc.x + h0.x) + bv.x;
    o.y = di * (acc.y + h0.y) + bv.y;
    o.z = di * (acc.z + h1.x) + bv.z;
    o.w = di * (acc.w + h1.y) + bv.w;
    if (relu) {
        o.x = fmaxf(o.x, 0.f); o.y = fmaxf(o.y, 0.f);
        o.z = fmaxf(o.z, 0.f); o.w = fmaxf(o.w, 0.f);
    }
    *(float4*)(outp + (size_t)t * NN * HH + (size_t)i * HH + c) = o;
}

// ---------------- GRU elementwise step ----------------
__global__ void gru_elem(int t) {
    int idx = blockIdx.x * blockDim.x + threadIdx.x;
    if (idx >= NN * HH) return;
    int n = idx >> 7, j = idx & 127;
    const float* gi = g_gi + ((size_t)t * NN + n) * H3;
    const float* gh = g_gh + (size_t)n * H3;
    float ir = gi[j], iz = gi[HH + j], in_ = gi[2 * HH + j];
    float hr = gh[j], hz = gh[HH + j], hn = gh[2 * HH + j];
    float hp = g_hst[idx];
    float r = 1.f / (1.f + expf(-(ir + hr)));
    float z = 1.f / (1.f + expf(-(iz + hz)));
    float nn = tanhf(in_ + r * hn);
    g_hst[idx] = (1.f - z) * nn + z * hp;
}

// ---------------- decoder ----------------
__global__ void decode_kernel(const int* __restrict__ ep, float* __restrict__ out) {
    int gid = blockIdx.x * blockDim.x + threadIdx.x;
    int w = gid >> 5, lane = gid & 31;
    if (w >= PP) return;
    int s = ep[w], d = ep[PP + w];
    float4 a = *(const float4*)&g_hst[(size_t)s * HH + lane * 4];
    float4 b = *(const float4*)&g_hst[(size_t)d * HH + lane * 4];
    float v = a.x * b.x + a.y * b.y + a.z * b.z + a.w * b.w;
#pragma unroll
    for (int off = 16; off; off >>= 1) v += __shfl_down_sync(0xffffffffu, v, off);
    if (lane == 0) out[w] = v;
}

// ---------------- launch ----------------
extern "C" void kernel_launch(void* const* d_in, const int* in_sizes, int n_in,
                              void* d_out, int out_size)
{
    const float* x_seq  = (const float*)d_in[0];
    const int* edge_index = (const int*)d_in[1];
    const int* edge_pairs = (const int*)d_in[2];
    const float* W1 = (const float*)d_in[3];
    const float* b1 = (const float*)d_in[4];
    const float* W2 = (const float*)d_in[5];
    const float* b2 = (const float*)d_in[6];
    const float* W3 = (const float*)d_in[7];
    const float* b3 = (const float*)d_in[8];
    const float* w_ih = (const float*)d_in[9];
    const float* w_hh = (const float*)d_in[10];
    const float* b_ih = (const float*)d_in[11];
    const float* b_hh = (const float*)d_in[12];
    float* out = (float*)d_out;

    float *bufB, *gi, *gh, *hst, *dinv;
    __half* hx;
    __nv_bfloat16 *wh, *wl;
    cudaGetSymbolAddress((void**)&hx,   g_hx);
    cudaGetSymbolAddress((void**)&bufB, g_bufB);
    cudaGetSymbolAddress((void**)&gi,   g_gi);
    cudaGetSymbolAddress((void**)&gh,   g_gh);
    cudaGetSymbolAddress((void**)&hst,  g_hst);
    cudaGetSymbolAddress((void**)&dinv, g_dinv);
    cudaGetSymbolAddress((void**)&wh,   g_wh);
    cudaGetSymbolAddress((void**)&wl,   g_wl);

    cudaFuncSetAttribute(mma_gemm, cudaFuncAttributeMaxDynamicSharedMemorySize, SMEM_MMA);

    // graph prep
    zero_kernel<<<(NN * HH + 255) / 256, 256>>>();
    deg_kernel<<<(TT * EE + 255) / 256, 256>>>(edge_index);
    dinv_kernel<<<(TT * NN + 255) / 256, 256>>>();
    scan_kernel<<<TT, 256>>>();
    fill_kernel<<<(TT * EE + 255) / 256, 256>>>(edge_index);
    split_weights<<<(147456 + 255) / 256, 256>>>(W1, W2, W3, w_ih, w_hh);

    const int MB = (TT * NN + 127) / 128;   // 2500
    dim3 gGather(NN / 8, TT);               // warp-per-node, 8 nodes/block

    // GCN stack; GEMM epilogue pre-scales by dinv and emits fp16 h'
    mma_gemm<<<dim3(MB, 1), 256, SMEM_MMA>>>(x_seq, wh,        wl,        nullptr, TT * NN, HH, nullptr, dinv, hx);
    gather_kernel<<<gGather, 256>>>(hx, bufB, b1, 1);
    mma_gemm<<<dim3(MB, 1), 256, SMEM_MMA>>>(bufB, wh + 16384, wl + 16384, nullptr, TT * NN, HH, nullptr, dinv, hx);
    gather_kernel<<<gGather, 256>>>(hx, bufB, b2, 1);
    mma_gemm<<<dim3(MB, 1), 256, SMEM_MMA>>>(bufB, wh + 32768, wl + 32768, nullptr, TT * NN, HH, nullptr, dinv, hx);
    gather_kernel<<<gGather, 256>>>(hx, bufB, b3, 0);
    // feats in bufB

    // GRU input projections (one big GEMM over all frames, fp32 out)
    mma_gemm<<<dim3(MB, 3), 256, SMEM_MMA>>>(bufB, wh + 49152, wl + 49152, gi, TT * NN, H3, b_ih, nullptr, nullptr);

    // GRU steps: gh GEMM (B resident in smem) + elementwise
    const int MBH = (NN + 127) / 128;       // 157
    for (int t = 0; t < TT; t++) {
        mma_gemm<<<dim3(MBH, 3), 256, SMEM_MMA>>>(hst, wh + 98304, wl + 98304, gh, NN, H3, b_hh, nullptr, nullptr);
        gru_elem<<<(NN * HH + 255) / 256, 256>>>(t);
    }

    decode_kernel<<<(PP * 32 + 255) / 256, 256>>>(edge_pairs, out);
}

// round 12
// speedup vs baseline: 1.6851x; 1.0237x over previous
#include <cuda_runtime.h>
#include <cuda_bf16.h>
#include <cuda_fp16.h>
#include <math.h>
#include <stdint.h>

#define TT 16
#define NN 20000
#define EE 320000
#define CC 128
#define HH 128
#define PP 100000
#define H3 384

#define ROWPAD 136            // bf16 per smem row (272 B = 17 x 16B: odd -> conflict-free ldmatrix)

// ---------------- scratch (device globals; no allocation allowed) ----------------
__device__ __half g_hx[(size_t)TT * NN * HH];    // fp16 h' (GEMM out, gather in)
__device__ float g_bufB[(size_t)TT * NN * HH];
__device__ __half g_gi[(size_t)TT * NN * H3];    // fp16 GRU input gates
__device__ __half g_gh[(size_t)NN * H3];         // fp16 GRU hidden gates
__device__ float g_hst[(size_t)NN * HH];
__device__ float g_dinv[TT * NN];
__device__ int   g_cnt[TT * NN];
__device__ int   g_rowptr[TT * (NN + 1)];
__device__ int   g_cursor[TT * NN];
__device__ int   g_csrsrc[TT * EE];
// split weights (bf16 hi/lo): [0,16384) W1^T, [16384,32768) W2^T, [32768,49152) W3^T,
// [49152,98304) w_ih, [98304,147456) w_hh   (all stored [n][k], k contiguous, K=128)
__device__ __nv_bfloat16 g_wh[147456];
__device__ __nv_bfloat16 g_wl[147456];

// ---------------- PTX helpers ----------------
__device__ __forceinline__ uint32_t smem_u32(const void* p) {
    uint32_t a;
    asm("{ .reg .u64 t; cvta.to.shared.u64 t, %1; cvt.u32.u64 %0, t; }" : "=r"(a) : "l"(p));
    return a;
}
__device__ __forceinline__ void ldsm_x4(uint32_t* r, uint32_t addr) {
    asm volatile("ldmatrix.sync.aligned.m8n8.x4.shared.b16 {%0,%1,%2,%3}, [%4];"
                 : "=r"(r[0]), "=r"(r[1]), "=r"(r[2]), "=r"(r[3]) : "r"(addr));
}
__device__ __forceinline__ void mma16816(float* d, const uint32_t* a, const uint32_t* b) {
    asm volatile(
        "mma.sync.aligned.m16n8k16.row.col.f32.bf16.bf16.f32 "
        "{%0,%1,%2,%3}, {%4,%5,%6,%7}, {%8,%9}, {%0,%1,%2,%3};"
        : "+f"(d[0]), "+f"(d[1]), "+f"(d[2]), "+f"(d[3])
        : "r"(a[0]), "r"(a[1]), "r"(a[2]), "r"(a[3]), "r"(b[0]), "r"(b[1]));
}
__device__ __forceinline__ uint32_t pack_bf2(__nv_bfloat16 a, __nv_bfloat16 b) {
    uint32_t r;
    asm("mov.b32 %0, {%1, %2};" : "=r"(r) : "h"(*(uint16_t*)&a), "h"(*(uint16_t*)&b));
    return r;
}

// ---------------- small utility kernels ----------------
__global__ void zero_kernel() {
    int idx = blockIdx.x * blockDim.x + threadIdx.x;
    if (idx < TT * NN) g_cnt[idx] = 0;
    if (idx < NN * HH) g_hst[idx] = 0.f;
}

__global__ void deg_kernel(const int* __restrict__ ei) {
    int idx = blockIdx.x * blockDim.x + threadIdx.x;
    if (idx >= TT * EE) return;
    int t = idx / EE, e = idx - t * EE;
    int dst = ei[(size_t)t * 2 * EE + EE + e];
    atomicAdd(&g_cnt[t * NN + dst], 1);
}

__global__ void dinv_kernel() {
    int idx = blockIdx.x * blockDim.x + threadIdx.x;
    if (idx >= TT * NN) return;
    g_dinv[idx] = rsqrtf((float)g_cnt[idx] + 1.0f);
}

__global__ void scan_kernel() {
    const int CH = 79;
    int t = blockIdx.x;
    int tx = threadIdx.x;
    int base = t * NN;
    int st = tx * CH, en = min(st + CH, NN);
    int s = 0;
    for (int i = st; i < en; i++) s += g_cnt[base + i];
    __shared__ int sh[256];
    sh[tx] = s;
    __syncthreads();
    for (int off = 1; off < 256; off <<= 1) {
        int v = (tx >= off) ? sh[tx - off] : 0;
        __syncthreads();
        sh[tx] += v;
        __syncthreads();
    }
    int run = sh[tx] - s;
    int roff = t * (NN + 1);
    for (int i = st; i < en; i++) {
        int c = g_cnt[base + i];
        g_rowptr[roff + i] = run;
        g_cursor[base + i] = run;
        run += c;
    }
    if (tx == 255) g_rowptr[roff + NN] = sh[255];
}

__global__ void fill_kernel(const int* __restrict__ ei) {
    int idx = blockIdx.x * blockDim.x + threadIdx.x;
    if (idx >= TT * EE) return;
    int t = idx / EE, e = idx - t * EE;
    int src = ei[(size_t)t * 2 * EE + e];
    int dst = ei[(size_t)t * 2 * EE + EE + e];
    int pos = atomicAdd(&g_cursor[t * NN + dst], 1);
    g_csrsrc[(size_t)t * EE + pos] = src;
}

// split weights into bf16 hi/lo pairs, storing [n][k] (k contiguous)
__global__ void split_weights(const float* __restrict__ W1, const float* __restrict__ W2,
                              const float* __restrict__ W3, const float* __restrict__ wih,
                              const float* __restrict__ whh) {
    int idx = blockIdx.x * blockDim.x + threadIdx.x;
    if (idx >= 147456) return;
    float x;
    if (idx < 49152) {
        int w = idx / 16384, r = idx - w * 16384;
        int n = r >> 7, k = r & 127;
        const float* W = (w == 0) ? W1 : ((w == 1) ? W2 : W3);
        x = W[k * 128 + n];              // transpose: W is [K][N]
    } else {
        int j = idx - 49152;
        const float* W = (j < 49152) ? wih : whh;
        int r = (j < 49152) ? j : j - 49152;
        x = W[r];                        // already [n][k]
    }
    __nv_bfloat16 h = __float2bfloat16(x);
    g_wh[idx] = h;
    g_wl[idx] = __float2bfloat16(x - __bfloat162float(h));
}

// ---------------- split-bf16 HMMA GEMM: C = A[M,128] @ B^T (+bias, *dscale) ----------------
// If Ch != nullptr, output is written as fp16 to Ch (stride Ntot); else fp32 to C.
#define SMEM_MMA (4 * 128 * ROWPAD * 2)
__global__ void __launch_bounds__(256) mma_gemm(
    const float* __restrict__ A, const __nv_bfloat16* __restrict__ Bh,
    const __nv_bfloat16* __restrict__ Bl, float* __restrict__ C,
    int M, int Ntot, const float* __restrict__ bias, const float* __restrict__ dscale,
    __half* __restrict__ Ch)
{
    extern __shared__ __nv_bfloat16 sm[];
    __nv_bfloat16* Ah = sm;                       // [128][ROWPAD]
    __nv_bfloat16* Al = sm + 128 * ROWPAD;
    __nv_bfloat16* Bsh = sm + 2 * 128 * ROWPAD;   // hi
    __nv_bfloat16* Bsl = sm + 3 * 128 * ROWPAD;   // lo

    const int tid = threadIdx.x;
    const int warp = tid >> 5, lane = tid & 31;
    const int wm = warp >> 1, wn = warp & 1;
    const int row0 = blockIdx.x * 128, col0 = blockIdx.y * 128;

#pragma unroll
    for (int i = 0; i < 16; i++) {
        int fi = tid + i * 256;
        int r = fi >> 5;
        int kc = (fi & 31) * 4;
        float4 v = make_float4(0.f, 0.f, 0.f, 0.f);
        int gr = row0 + r;
        if (gr < M) v = *(const float4*)(A + (size_t)gr * 128 + kc);
        __nv_bfloat16 hx = __float2bfloat16(v.x), hy = __float2bfloat16(v.y);
        __nv_bfloat16 hz = __float2bfloat16(v.z), hw = __float2bfloat16(v.w);
        __nv_bfloat16 lx = __float2bfloat16(v.x - __bfloat162float(hx));
        __nv_bfloat16 ly = __float2bfloat16(v.y - __bfloat162float(hy));
        __nv_bfloat16 lz = __float2bfloat16(v.z - __bfloat162float(hz));
        __nv_bfloat16 lw = __float2bfloat16(v.w - __bfloat162float(hw));
        *(uint2*)(Ah + r * ROWPAD + kc) = make_uint2(pack_bf2(hx, hy), pack_bf2(hz, hw));
        *(uint2*)(Al + r * ROWPAD + kc) = make_uint2(pack_bf2(lx, ly), pack_bf2(lz, lw));
    }
#pragma unroll
    for (int i = 0; i < 16; i++) {
        int fi = tid + i * 256;
        int m = fi >> 11;
        int j = fi & 2047;
        int r = j >> 4;
        int kc = (j & 15) * 8;
        const __nv_bfloat16* src = m ? Bl : Bh;
        uint4 v = *(const uint4*)(src + (size_t)(col0 + r) * 128 + kc);
        __nv_bfloat16* dst = m ? Bsl : Bsh;
        *(uint4*)(dst + r * ROWPAD + kc) = v;
    }
    __syncthreads();

    const uint32_t sbase = smem_u32(sm);
    float acc[2][8][4];
#pragma unroll
    for (int mt = 0; mt < 2; mt++)
#pragma unroll
        for (int nt = 0; nt < 8; nt++)
#pragma unroll
            for (int q = 0; q < 4; q++) acc[mt][nt][q] = 0.f;

    const uint32_t a_lane = (uint32_t)((wm * 32 + (lane & 15)) * ROWPAD + (lane >> 4) * 8) * 2;
    const uint32_t b_lane = (uint32_t)((wn * 64 + (lane & 7) + ((lane >> 4) << 3)) * ROWPAD
                                       + ((lane >> 3) & 1) * 8) * 2;

#pragma unroll
    for (int term = 0; term < 3; term++) {
        const uint32_t abase = sbase + ((term == 1) ? (128 * ROWPAD * 2) : 0) + a_lane;
        const uint32_t bbase = sbase + ((term == 2) ? (3 * 128 * ROWPAD * 2) : (2 * 128 * ROWPAD * 2)) + b_lane;
#pragma unroll
        for (int kc = 0; kc < 8; kc++) {
            uint32_t af[2][4], bf[4][4];
#pragma unroll
            for (int mt = 0; mt < 2; mt++)
                ldsm_x4(af[mt], abase + (uint32_t)(mt * 16 * ROWPAD + kc * 16) * 2);
#pragma unroll
            for (int n2 = 0; n2 < 4; n2++)
                ldsm_x4(bf[n2], bbase + (uint32_t)(n2 * 16 * ROWPAD + kc * 16) * 2);
#pragma unroll
            for (int mt = 0; mt < 2; mt++)
#pragma unroll
                for (int nt = 0; nt < 8; nt++)
                    mma16816(acc[mt][nt], af[mt], &bf[nt >> 1][(nt & 1) * 2]);
        }
    }

#pragma unroll
    for (int mt = 0; mt < 2; mt++) {
        int r_lo = row0 + wm * 32 + mt * 16 + (lane >> 2);
        int r_hi = r_lo + 8;
        float ds_lo = 1.f, ds_hi = 1.f;
        if (dscale) {
            if (r_lo < M) ds_lo = dscale[r_lo];
            if (r_hi < M) ds_hi = dscale[r_hi];
        }
#pragma unroll
        for (int nt = 0; nt < 8; nt++) {
            int gc = col0 + wn * 64 + nt * 8 + (lane & 3) * 2;
            float bx = 0.f, by = 0.f;
            if (bias) { bx = bias[gc]; by = bias[gc + 1]; }
            float v0l = acc[mt][nt][0] * ds_lo + bx, v1l = acc[mt][nt][1] * ds_lo + by;
            float v0h = acc[mt][nt][2] * ds_hi + bx, v1h = acc[mt][nt][3] * ds_hi + by;
            if (Ch) {
                if (r_lo < M)
                    *(__half2*)(Ch + (size_t)r_lo * Ntot + gc) = __floats2half2_rn(v0l, v1l);
                if (r_hi < M)
                    *(__half2*)(Ch + (size_t)r_hi * Ntot + gc) = __floats2half2_rn(v0h, v1h);
            } else {
                if (r_lo < M)
                    *(float2*)(C + (size_t)r_lo * Ntot + gc) = make_float2(v0l, v1l);
                if (r_hi < M)
                    *(float2*)(C + (size_t)r_hi * Ntot + gc) = make_float2(v0h, v1h);
            }
        }
    }
}

// ---------------- GCN aggregation: warp-per-node gather on fp16 h' ----------------
// hp holds h' = dinv[row] * (X W) in fp16. out = dinv[i]*(sum_s h'[s] + h'[i]) + bias (relu)
__global__ void __launch_bounds__(256) gather_kernel(
    const __half* __restrict__ hp, float* __restrict__ outp,
    const float* __restrict__ bias, int relu)
{
    int t = blockIdx.y;
    int warp = threadIdx.x >> 5, lane = threadIdx.x & 31;
    int i = blockIdx.x * 8 + warp;
    if (i >= NN) return;
    int roff = t * (NN + 1);
    int ks = g_rowptr[roff + i];
    int ke = g_rowptr[roff + i + 1];
    const int* __restrict__ srcs = g_csrsrc + (size_t)t * EE;
    const __half* __restrict__ hf = hp + (size_t)t * NN * HH;
    int c = lane * 4;
    float4 acc = make_float4(0.f, 0.f, 0.f, 0.f);
    int k = ks;
    for (; k + 1 < ke; k += 2) {
        int s0 = __ldg(srcs + k);
        int s1 = __ldg(srcs + k + 1);
        uint2 r0 = *(const uint2*)(hf + (size_t)s0 * HH + c);
        uint2 r1 = *(const uint2*)(hf + (size_t)s1 * HH + c);
        float2 a0 = __half22float2(*(const __half2*)&r0.x);
        float2 a1 = __half22float2(*(const __half2*)&r0.y);
        float2 b0 = __half22float2(*(const __half2*)&r1.x);
        float2 b1 = __half22float2(*(const __half2*)&r1.y);
        acc.x += a0.x + b0.x; acc.y += a0.y + b0.y;
        acc.z += a1.x + b1.x; acc.w += a1.y + b1.y;
    }
    if (k < ke) {
        int s = __ldg(srcs + k);
        uint2 r0 = *(const uint2*)(hf + (size_t)s * HH + c);
        float2 a0 = __half22float2(*(const __half2*)&r0.x);
        float2 a1 = __half22float2(*(const __half2*)&r0.y);
        acc.x += a0.x; acc.y += a0.y; acc.z += a1.x; acc.w += a1.y;
    }
    float di = g_dinv[t * NN + i];
    uint2 rs = *(const uint2*)(hf + (size_t)i * HH + c);
    float2 h0 = __half22float2(*(const __half2*)&rs.x);
    float2 h1 = __half22float2(*(const __half2*)&rs.y);
    float4 bv = *(const float4*)(bias + c);
    float4 o;
    o.x = di * (acc.x + h0.x) + bv.x;
    o.y = di * (acc.y + h0.y) + bv.y;
    o.z = di * (acc.z + h1.x) + bv.z;
    o.w = di * (acc.w + h1.y) + bv.w;
    if (relu) {
        o.x = fmaxf(o.x, 0.f); o.y = fmaxf(o.y, 0.f);
        o.z = fmaxf(o.z, 0.f); o.w = fmaxf(o.w, 0.f);
    }
    *(float4*)(outp + (size_t)t * NN * HH + (size_t)i * HH + c) = o;
}

// ---------------- GRU elementwise step (fp16 gate buffers) ----------------
__global__ void gru_elem(int t) {
    int idx = blockIdx.x * blockDim.x + threadIdx.x;
    if (idx >= NN * HH) return;
    int n = idx >> 7, j = idx & 127;
    const __half* gi = g_gi + ((size_t)t * NN + n) * H3;
    const __half* gh = g_gh + (size_t)n * H3;
    float ir = __half2float(gi[j]), iz = __half2float(gi[HH + j]), in_ = __half2float(gi[2 * HH + j]);
    float hr = __half2float(gh[j]), hz = __half2float(gh[HH + j]), hn = __half2float(gh[2 * HH + j]);
    float hp = g_hst[idx];
    float r = 1.f / (1.f + expf(-(ir + hr)));
    float z = 1.f / (1.f + expf(-(iz + hz)));
    float nn = tanhf(in_ + r * hn);
    g_hst[idx] = (1.f - z) * nn + z * hp;
}

// ---------------- decoder ----------------
__global__ void decode_kernel(const int* __restrict__ ep, float* __restrict__ out) {
    int gid = blockIdx.x * blockDim.x + threadIdx.x;
    int w = gid >> 5, lane = gid & 31;
    if (w >= PP) return;
    int s = ep[w], d = ep[PP + w];
    float4 a = *(const float4*)&g_hst[(size_t)s * HH + lane * 4];
    float4 b = *(const float4*)&g_hst[(size_t)d * HH + lane * 4];
    float v = a.x * b.x + a.y * b.y + a.z * b.z + a.w * b.w;
#pragma unroll
    for (int off = 16; off; off >>= 1) v += __shfl_down_sync(0xffffffffu, v, off);
    if (lane == 0) out[w] = v;
}

// ---------------- launch ----------------
extern "C" void kernel_launch(void* const* d_in, const int* in_sizes, int n_in,
                              void* d_out, int out_size)
{
    const float* x_seq  = (const float*)d_in[0];
    const int* edge_index = (const int*)d_in[1];
    const int* edge_pairs = (const int*)d_in[2];
    const float* W1 = (const float*)d_in[3];
    const float* b1 = (const float*)d_in[4];
    const float* W2 = (const float*)d_in[5];
    const float* b2 = (const float*)d_in[6];
    const float* W3 = (const float*)d_in[7];
    const float* b3 = (const float*)d_in[8];
    const float* w_ih = (const float*)d_in[9];
    const float* w_hh = (const float*)d_in[10];
    const float* b_ih = (const float*)d_in[11];
    const float* b_hh = (const float*)d_in[12];
    float* out = (float*)d_out;

    float *bufB, *hst, *dinv;
    __half *hx, *gi, *gh;
    __nv_bfloat16 *wh, *wl;
    cudaGetSymbolAddress((void**)&hx,   g_hx);
    cudaGetSymbolAddress((void**)&bufB, g_bufB);
    cudaGetSymbolAddress((void**)&gi,   g_gi);
    cudaGetSymbolAddress((void**)&gh,   g_gh);
    cudaGetSymbolAddress((void**)&hst,  g_hst);
    cudaGetSymbolAddress((void**)&dinv, g_dinv);
    cudaGetSymbolAddress((void**)&wh,   g_wh);
    cudaGetSymbolAddress((void**)&wl,   g_wl);

    cudaFuncSetAttribute(mma_gemm, cudaFuncAttributeMaxDynamicSharedMemorySize, SMEM_MMA);

    // graph prep
    zero_kernel<<<(NN * HH + 255) / 256, 256>>>();
    deg_kernel<<<(TT * EE + 255) / 256, 256>>>(edge_index);
    dinv_kernel<<<(TT * NN + 255) / 256, 256>>>();
    scan_kernel<<<TT, 256>>>();
    fill_kernel<<<(TT * EE + 255) / 256, 256>>>(edge_index);
    split_weights<<<(147456 + 255) / 256, 256>>>(W1, W2, W3, w_ih, w_hh);

    const int MB = (TT * NN + 127) / 128;   // 2500
    dim3 gGather(NN / 8, TT);               // warp-per-node, 8 nodes/block

    // GCN stack; GEMM epilogue pre-scales by dinv and emits fp16 h'
    mma_gemm<<<dim3(MB, 1), 256, SMEM_MMA>>>(x_seq, wh,        wl,        nullptr, TT * NN, HH, nullptr, dinv, hx);
    gather_kernel<<<gGather, 256>>>(hx, bufB, b1, 1);
    mma_gemm<<<dim3(MB, 1), 256, SMEM_MMA>>>(bufB, wh + 16384, wl + 16384, nullptr, TT * NN, HH, nullptr, dinv, hx);
    gather_kernel<<<gGather, 256>>>(hx, bufB, b2, 1);
    mma_gemm<<<dim3(MB, 1), 256, SMEM_MMA>>>(bufB, wh + 32768, wl + 32768, nullptr, TT * NN, HH, nullptr, dinv, hx);
    gather_kernel<<<gGather, 256>>>(hx, bufB, b3, 0);
    // feats in bufB

    // GRU input projections (one big GEMM over all frames, fp16 out)
    mma_gemm<<<dim3(MB, 3), 256, SMEM_MMA>>>(bufB, wh + 49152, wl + 49152, nullptr, TT * NN, H3, b_ih, nullptr, gi);

    // GRU steps: gh GEMM (fp16 out, B resident in smem) + elementwise
    const int MBH = (NN + 127) / 128;       // 157
    for (int t = 0; t < TT; t++) {
        mma_gemm<<<dim3(MBH, 3), 256, SMEM_MMA>>>(hst, wh + 98304, wl + 98304, nullptr, NN, H3, b_hh, nullptr, gh);
        gru_elem<<<(NN * HH + 255) / 256, 256>>>(t);
    }

    decode_kernel<<<(PP * 32 + 255) / 256, 256>>>(edge_pairs, out);
}